// round 4
// baseline (speedup 1.0000x reference)
#include <cuda_runtime.h>

typedef unsigned long long u64;

#define LN   256
#define BN   128
#define DN   512
#define HN   512
#define H3N  1536
#define NPN  (LN*BN)          // 32768
#define OUTB (LN*2*HN)        // 262144 floats per batch in outputs region

// ---------------- device scratch (no allocations allowed) ----------------
__device__ float    g_XG[(size_t)NPN*H3N];     // x-projections (reused per pass, ~201 MB)
__device__ float    g_HG[(size_t)NPN*H3N];     // h@Uh results per level       (~201 MB)
__device__ float    g_A [(size_t)NPN*HN];      // gathered h_prev rows          (~64 MB)
__device__ unsigned g_pairs_dt[NPN];           // (node<<8)|b, grouped by level
__device__ unsigned g_pairs_td[NPN];
__device__ int      g_choff[BN*257];           // child CSR offsets per batch
__device__ int      g_chlist[BN*LN];           // child lists (ascending node order)
__device__ int      g_base_dt[258];            // level -> first row in pairs
__device__ int      g_base_td[258];
__device__ int      g_nlev_dt;
__device__ int      g_nlev_td;
__device__ unsigned g_bar;

// ---------------- f32x2 helpers ----------------
__device__ __forceinline__ u64 pk2(float x) {
    u64 r; asm("mov.b64 %0, {%1, %1};" : "=l"(r) : "f"(x)); return r;
}
__device__ __forceinline__ void fma2(u64& d, u64 a, u64 b) {
    asm("fma.rn.f32x2 %0, %1, %2, %0;" : "+l"(d) : "l"(a), "l"(b));
}
__device__ __forceinline__ float2 up2(u64 v) {
    float2 r; asm("mov.b64 {%0, %1}, %2;" : "=f"(r.x), "=f"(r.y) : "l"(v)); return r;
}
union F4U { float4 v; u64 d[2]; };

__device__ __forceinline__ float sgm(float x) { return 1.0f / (1.0f + __expf(-x)); }
__device__ __forceinline__ float4 f4add(float4 a, float4 b) {
    a.x += b.x; a.y += b.y; a.z += b.z; a.w += b.w; return a;
}

// ---------------- grid barrier (all CTAs resident; 1 CTA/SM) ----------------
__device__ __forceinline__ void gbar(unsigned* ep) {
    __syncthreads();
    if (threadIdx.x == 0) {
        *ep += gridDim.x;
        __threadfence();
        atomicAdd(&g_bar, 1u);
        while (*(volatile unsigned*)&g_bar < *ep) __nanosleep(64);
        __threadfence();
    }
    __syncthreads();
}

// =======================================================================
// Schedule kernel: one block, 128 threads (one tree per thread).
// =======================================================================
__global__ void k_sched(const int* __restrict__ pidx, const float* __restrict__ pval) {
    __shared__ int s_cntd[LN], s_cntt[LN], s_based[257], s_baset[257];
    __shared__ int s_filld[LN], s_fillt[LN];
    __shared__ int s_maxd, s_maxt;
    const int b = threadIdx.x;

    for (int i = b; i < LN; i += BN) { s_cntd[i]=0; s_cntt[i]=0; s_filld[i]=0; s_fillt[i]=0; }
    if (b == 0) { s_maxd = 0; s_maxt = 0; g_bar = 0u; }
    __syncthreads();

    int par[LN]; unsigned char rootf[LN];
    short hl[LN], dl[LN];
    for (int i = 0; i < LN; i++) {
        par[i]   = pidx[i*BN + b];
        rootf[i] = (pval[i*BN + b] == 0.0f) ? 1 : 0;
    }
    // td depth (parents precede children in index order)
    for (int i = 0; i < LN; i++) dl[i] = rootf[i] ? 0 : (short)(dl[par[i]] + 1);
    // dt height (children have larger index; descending relaxation)
    for (int i = 0; i < LN; i++) hl[i] = 0;
    for (int i = LN-1; i >= 1; i--)
        if (!rootf[i]) { short c = (short)(hl[i] + 1); if (c > hl[par[i]]) hl[par[i]] = c; }

    int mxd = 0, mxt = 0;
    for (int i = 0; i < LN; i++) {
        atomicAdd(&s_cntd[hl[i]], 1);
        atomicAdd(&s_cntt[dl[i]], 1);
        if (hl[i] > mxd) mxd = hl[i];
        if (dl[i] > mxt) mxt = dl[i];
    }
    atomicMax(&s_maxd, mxd);
    atomicMax(&s_maxt, mxt);

    // child CSR (ascending child order -> deterministic sums)
    int ccnt[LN];
    for (int p = 0; p < LN; p++) ccnt[p] = 0;
    for (int i = 1; i < LN; i++) if (!rootf[i]) ccnt[par[i]]++;
    int cur[LN]; int off = 0;
    for (int p = 0; p < LN; p++) { g_choff[b*257 + p] = off; cur[p] = off; off += ccnt[p]; }
    g_choff[b*257 + 256] = off;
    for (int i = 1; i < LN; i++)
        if (!rootf[i]) { int q = par[i]; g_chlist[b*LN + cur[q]++] = i; }

    __syncthreads();
    if (b == 0) {
        int ad = 0, at = 0;
        for (int l = 0; l < LN; l++) {
            s_based[l] = ad; ad += s_cntd[l];
            s_baset[l] = at; at += s_cntt[l];
        }
        s_based[LN] = ad; s_baset[LN] = at;
        g_nlev_dt = s_maxd + 1;
        g_nlev_td = s_maxt + 1;
        for (int l = 0; l <= LN; l++) { g_base_dt[l] = s_based[l]; g_base_td[l] = s_baset[l]; }
    }
    __syncthreads();

    // place pairs (intra-level order nondeterministic; per-(node,b) results order-invariant)
    for (int i = 0; i < LN; i++) {
        int ld = hl[i];
        int k1 = atomicAdd(&s_filld[ld], 1);
        g_pairs_dt[s_based[ld] + k1] = ((unsigned)i << 8) | (unsigned)b;
        int lt = dl[i];
        int k2 = atomicAdd(&s_fillt[lt], 1);
        g_pairs_td[s_baset[lt] + k2] = ((unsigned)i << 8) | (unsigned)b;
    }
}

// =======================================================================
// fp32 GEMM (big path): C[M x 1536] = A[M x 512] @ B[512 x 1536] (+ bias)
// 128x128 tiles, 256 threads, K-chunks of 32, register double buffering,
// f32x2 accumulators (8 rows x 4 col-pairs per thread).
// =======================================================================
__device__ void gemm_big(const float* __restrict__ A, int M,
                         const float* __restrict__ B, const float* __restrict__ bias,
                         float* __restrict__ C, float* sm)
{
    float* As = sm;             // [32][132]
    float* Bs = sm + 32*132;    // [32][128]
    const int tid  = threadIdx.x;
    const int trow = tid >> 4, tcol = tid & 15;
    const int mtiles = (M + 127) >> 7;
    const int total  = mtiles * 12;

    for (int t = blockIdx.x; t < total; t += gridDim.x) {
        const int row0 = (t / 12) << 7;
        const int col0 = (t % 12) << 7;
        float4 ra[4], rb[4];
        u64 acc[8][4];
        #pragma unroll
        for (int r = 0; r < 8; r++)
            #pragma unroll
            for (int c = 0; c < 4; c++) acc[r][c] = 0ULL;

        auto loadchunk = [&](int kc) {
            #pragma unroll
            for (int i = 0; i < 4; i++) {
                int f = tid + (i << 8); int rr = f >> 3, kq = f & 7;
                int grow = row0 + rr;
                ra[i] = (grow < M) ? *(const float4*)&A[(size_t)grow*DN + (kc<<5) + (kq<<2)]
                                   : make_float4(0.f, 0.f, 0.f, 0.f);
            }
            #pragma unroll
            for (int i = 0; i < 4; i++) {
                int f = tid + (i << 8); int kr = f >> 5, nq = f & 31;
                rb[i] = *(const float4*)&B[(size_t)((kc<<5) + kr)*H3N + col0 + (nq<<2)];
            }
        };
        auto storechunk = [&]() {
            #pragma unroll
            for (int i = 0; i < 4; i++) {
                int f = tid + (i << 8); int rr = f >> 3, kq = f & 7;
                As[(kq*4+0)*132 + rr] = ra[i].x;
                As[(kq*4+1)*132 + rr] = ra[i].y;
                As[(kq*4+2)*132 + rr] = ra[i].z;
                As[(kq*4+3)*132 + rr] = ra[i].w;
            }
            #pragma unroll
            for (int i = 0; i < 4; i++) {
                int f = tid + (i << 8); int kr = f >> 5, nq = f & 31;
                *(float4*)&Bs[kr*128 + (nq<<2)] = rb[i];
            }
        };

        loadchunk(0);
        __syncthreads();
        storechunk();
        __syncthreads();

        for (int kc = 0; kc < 16; kc++) {
            if (kc < 15) loadchunk(kc + 1);
            #pragma unroll 8
            for (int k = 0; k < 32; k++) {
                float4 a0 = *(const float4*)&As[k*132 + (trow<<3)];
                float4 a1 = *(const float4*)&As[k*132 + (trow<<3) + 4];
                F4U bu0, bu1;
                bu0.v = *(const float4*)&Bs[k*128 + (tcol<<3)];
                bu1.v = *(const float4*)&Bs[k*128 + (tcol<<3) + 4];
                u64 b0 = bu0.d[0], b1 = bu0.d[1], b2 = bu1.d[0], b3 = bu1.d[1];
                float av[8] = {a0.x, a0.y, a0.z, a0.w, a1.x, a1.y, a1.z, a1.w};
                #pragma unroll
                for (int r = 0; r < 8; r++) {
                    u64 ap = pk2(av[r]);
                    fma2(acc[r][0], ap, b0);
                    fma2(acc[r][1], ap, b1);
                    fma2(acc[r][2], ap, b2);
                    fma2(acc[r][3], ap, b3);
                }
            }
            if (kc < 15) { __syncthreads(); storechunk(); __syncthreads(); }
        }

        float bv[8];
        if (bias) {
            float4 c0 = *(const float4*)&bias[col0 + (tcol<<3)];
            float4 c1 = *(const float4*)&bias[col0 + (tcol<<3) + 4];
            bv[0]=c0.x; bv[1]=c0.y; bv[2]=c0.z; bv[3]=c0.w;
            bv[4]=c1.x; bv[5]=c1.y; bv[6]=c1.z; bv[7]=c1.w;
        } else {
            #pragma unroll
            for (int c = 0; c < 8; c++) bv[c] = 0.0f;
        }
        #pragma unroll
        for (int r = 0; r < 8; r++) {
            int grow = row0 + (trow<<3) + r;
            if (grow < M) {
                float2 p0 = up2(acc[r][0]), p1 = up2(acc[r][1]);
                float2 p2 = up2(acc[r][2]), p3 = up2(acc[r][3]);
                float4 lo = make_float4(p0.x+bv[0], p0.y+bv[1], p1.x+bv[2], p1.y+bv[3]);
                float4 hi = make_float4(p2.x+bv[4], p2.y+bv[5], p3.x+bv[6], p3.y+bv[7]);
                float* cp = &C[(size_t)grow*H3N + col0 + (tcol<<3)];
                *(float4*)cp = lo;
                *(float4*)(cp + 4) = hi;
            }
        }
    }
}

// =======================================================================
// fp32 GEMM (small path, M<=2048): 64x64 tiles, 4x more parallelism and
// 4x lower per-tile latency for the shallow-level tail.
// =======================================================================
__device__ void gemm_small(const float* __restrict__ A, int M,
                           const float* __restrict__ B, const float* __restrict__ bias,
                           float* __restrict__ C, float* sm)
{
    float* As = sm;            // [32][68]
    float* Bs = sm + 32*68;    // [32][64]
    const int tid  = threadIdx.x;
    const int trow = tid >> 4, tcol = tid & 15;
    const int mtiles = (M + 63) >> 6;
    const int total  = mtiles * 24;

    for (int t = blockIdx.x; t < total; t += gridDim.x) {
        const int row0 = (t / 24) << 6;
        const int col0 = (t % 24) << 6;
        float4 ra, rb;
        u64 acc[4][2];
        #pragma unroll
        for (int r = 0; r < 4; r++) { acc[r][0] = 0ULL; acc[r][1] = 0ULL; }

        auto loadchunk = [&](int kc) {
            { int rr = tid >> 2, kq = tid & 3;      // A: 64 rows x 32 k = 256 float4
              int grow = row0 + rr;
              ra = (grow < M) ? *(const float4*)&A[(size_t)grow*DN + (kc<<5) + (kq<<3) + ((tid&1)? 4:0)]
                              : make_float4(0.f,0.f,0.f,0.f);
            }
            { int kr = tid >> 4, nq = tid & 15;     // B: 32 k x 64 cols x2 rows per thread
              rb = *(const float4*)&B[(size_t)((kc<<5) + kr)*H3N + col0 + (nq<<2)];
            }
        };
        // NOTE: A-load above packs 8 floats/row-pair awkwardly; use a simpler exact scheme:
        auto loadchunkA = [&](int kc, float4& r0, float4& r1) {
            int f0 = tid, f1 = tid + 256;           // 512 float4 = 64 rows x 8 kquads
            int rr0 = f0 >> 3, kq0 = f0 & 7;
            int rr1 = f1 >> 3, kq1 = f1 & 7;
            int g0 = row0 + rr0, g1 = row0 + rr1;
            r0 = (g0 < M) ? *(const float4*)&A[(size_t)g0*DN + (kc<<5) + (kq0<<2)] : make_float4(0,0,0,0);
            r1 = (g1 < M) ? *(const float4*)&A[(size_t)g1*DN + (kc<<5) + (kq1<<2)] : make_float4(0,0,0,0);
        };
        auto storechunkA = [&](float4 r0, float4 r1) {
            int f0 = tid, f1 = tid + 256;
            int rr0 = f0 >> 3, kq0 = f0 & 7;
            int rr1 = f1 >> 3, kq1 = f1 & 7;
            As[(kq0*4+0)*68 + rr0] = r0.x; As[(kq0*4+1)*68 + rr0] = r0.y;
            As[(kq0*4+2)*68 + rr0] = r0.z; As[(kq0*4+3)*68 + rr0] = r0.w;
            As[(kq1*4+0)*68 + rr1] = r1.x; As[(kq1*4+1)*68 + rr1] = r1.y;
            As[(kq1*4+2)*68 + rr1] = r1.z; As[(kq1*4+3)*68 + rr1] = r1.w;
        };
        auto storechunkB = [&]() {
            int kr = tid >> 4, nq = tid & 15;       // 32 k x 16 quads = 256 float4 in B? 32*64=2048 floats=512 f4; need 2/thread
            *(float4*)&Bs[kr*64 + (nq<<2)] = rb;
        };
        auto loadchunkB2 = [&](int kc, float4& r0, float4& r1) {
            int f0 = tid, f1 = tid + 256;           // 512 float4 = 32 k x 16 quads
            int k0 = f0 >> 4, n0 = f0 & 15;
            int k1 = f1 >> 4, n1 = f1 & 15;
            r0 = *(const float4*)&B[(size_t)((kc<<5) + k0)*H3N + col0 + (n0<<2)];
            r1 = *(const float4*)&B[(size_t)((kc<<5) + k1)*H3N + col0 + (n1<<2)];
        };
        auto storechunkB2 = [&](float4 r0, float4 r1) {
            int f0 = tid, f1 = tid + 256;
            int k0 = f0 >> 4, n0 = f0 & 15;
            int k1 = f1 >> 4, n1 = f1 & 15;
            *(float4*)&Bs[k0*64 + (n0<<2)] = r0;
            *(float4*)&Bs[k1*64 + (n1<<2)] = r1;
        };
        (void)loadchunk; (void)storechunkB; (void)ra; (void)rb;

        float4 a0, a1, b0, b1;
        loadchunkA(0, a0, a1);
        loadchunkB2(0, b0, b1);
        __syncthreads();
        storechunkA(a0, a1);
        storechunkB2(b0, b1);
        __syncthreads();

        for (int kc = 0; kc < 16; kc++) {
            if (kc < 15) { loadchunkA(kc+1, a0, a1); loadchunkB2(kc+1, b0, b1); }
            #pragma unroll 8
            for (int k = 0; k < 32; k++) {
                float4 av = *(const float4*)&As[k*68 + (trow<<2)];
                F4U bu; bu.v = *(const float4*)&Bs[k*64 + (tcol<<2)];
                u64 bb0 = bu.d[0], bb1 = bu.d[1];
                float avv[4] = {av.x, av.y, av.z, av.w};
                #pragma unroll
                for (int r = 0; r < 4; r++) {
                    u64 ap = pk2(avv[r]);
                    fma2(acc[r][0], ap, bb0);
                    fma2(acc[r][1], ap, bb1);
                }
            }
            if (kc < 15) { __syncthreads(); storechunkA(a0, a1); storechunkB2(b0, b1); __syncthreads(); }
        }

        float bv[4];
        if (bias) {
            float4 c0 = *(const float4*)&bias[col0 + (tcol<<2)];
            bv[0]=c0.x; bv[1]=c0.y; bv[2]=c0.z; bv[3]=c0.w;
        } else { bv[0]=bv[1]=bv[2]=bv[3]=0.0f; }
        #pragma unroll
        for (int r = 0; r < 4; r++) {
            int grow = row0 + (trow<<2) + r;
            if (grow < M) {
                float2 p0 = up2(acc[r][0]), p1 = up2(acc[r][1]);
                float4 v = make_float4(p0.x+bv[0], p0.y+bv[1], p1.x+bv[2], p1.y+bv[3]);
                *(float4*)&C[(size_t)grow*H3N + col0 + (tcol<<2)] = v;
            }
        }
    }
}

__device__ __forceinline__ void gemm512(const float* A, int M, const float* B,
                                        const float* bias, float* C, float* sm)
{
    if (M <= 2048) gemm_small(A, M, B, bias, C, sm);
    else           gemm_big  (A, M, B, bias, C, sm);
}

// ---------------- gather phases ----------------
__device__ void gather_dt(int r0, int r1, const float* __restrict__ out)
{
    int g = blockIdx.x*blockDim.x + threadIdx.x;
    int lane = g & 31, warp = g >> 5, nw = (gridDim.x*blockDim.x) >> 5;
    for (int row = r0 + warp; row < r1; row += nw) {
        unsigned p = g_pairs_dt[row]; int node = p >> 8, b = p & 255;
        int cs = g_choff[b*257 + node], ce = g_choff[b*257 + node + 1];
        float4 a0 = make_float4(0,0,0,0), a1 = a0, a2 = a0, a3 = a0;
        for (int c = cs; c < ce; c++) {
            const float4* src = (const float4*)&out[(size_t)b*OUTB + (size_t)g_chlist[b*LN + c]*(2*HN)];
            a0 = f4add(a0, src[lane]);
            a1 = f4add(a1, src[lane + 32]);
            a2 = f4add(a2, src[lane + 64]);
            a3 = f4add(a3, src[lane + 96]);
        }
        float4* dst = (float4*)&g_A[(size_t)row*HN];
        dst[lane] = a0; dst[lane+32] = a1; dst[lane+64] = a2; dst[lane+96] = a3;
    }
}

__device__ void gather_td(int r0, int r1, const float* __restrict__ out,
                          const int* __restrict__ pidx)
{
    int g = blockIdx.x*blockDim.x + threadIdx.x;
    int lane = g & 31, warp = g >> 5, nw = (gridDim.x*blockDim.x) >> 5;
    for (int row = r0 + warp; row < r1; row += nw) {
        unsigned p = g_pairs_td[row]; int node = p >> 8, b = p & 255;
        int parent = pidx[node*BN + b];
        const float4* src = (const float4*)&out[(size_t)b*OUTB + (size_t)parent*(2*HN) + HN];
        float4* dst = (float4*)&g_A[(size_t)row*HN];
        dst[lane]    = src[lane];
        dst[lane+32] = src[lane+32];
        dst[lane+64] = src[lane+64];
        dst[lane+96] = src[lane+96];
    }
}

// ---------------- gate epilogue (GRU nonlinearity) ----------------
__device__ void gates_range(int r0, int r1, int passoff, int haveH,
                            const float* __restrict__ xgb, float* __restrict__ out,
                            const unsigned* __restrict__ pairs)
{
    int total = (r1 - r0) << 7;   // float4 elements
    int gsz = gridDim.x * blockDim.x;
    for (int e = blockIdx.x*blockDim.x + threadIdx.x; e < total; e += gsz) {
        int row = r0 + (e >> 7);
        int j4  = (e & 127) << 2;
        unsigned p = pairs[row]; int node = p >> 8, b = p & 255;
        const float* xg = xgb + (size_t)(node*BN + b) * H3N;
        float4 xr = *(const float4*)&xg[j4];
        float4 xz = *(const float4*)&xg[HN + j4];
        float4 xn = *(const float4*)&xg[2*HN + j4];
        float4 hr = make_float4(0,0,0,0), hz = hr, hn = hr, hp = hr;
        if (haveH) {
            const float* hg = g_HG + (size_t)row * H3N;
            hr = *(const float4*)&hg[j4];
            hz = *(const float4*)&hg[HN + j4];
            hn = *(const float4*)&hg[2*HN + j4];
            hp = *(const float4*)&g_A[(size_t)row*HN + j4];
        }
        float4 o;
        { float r_=sgm(xr.x+hr.x), z_=sgm(xz.x+hz.x), n_=tanhf(xn.x + r_*hn.x); o.x=(1.f-z_)*n_ + z_*hp.x; }
        { float r_=sgm(xr.y+hr.y), z_=sgm(xz.y+hz.y), n_=tanhf(xn.y + r_*hn.y); o.y=(1.f-z_)*n_ + z_*hp.y; }
        { float r_=sgm(xr.z+hr.z), z_=sgm(xz.z+hz.z), n_=tanhf(xn.z + r_*hn.z); o.z=(1.f-z_)*n_ + z_*hp.z; }
        { float r_=sgm(xr.w+hr.w), z_=sgm(xz.w+hz.w), n_=tanhf(xn.w + r_*hn.w); o.w=(1.f-z_)*n_ + z_*hp.w; }
        *(float4*)&out[(size_t)b*OUTB + (size_t)node*(2*HN) + passoff + j4] = o;
    }
}

// =======================================================================
// Persistent main kernel.
// =======================================================================
__global__ void __launch_bounds__(256, 1) k_main(
    const float* __restrict__ emb,
    const float* __restrict__ dtWx, const float* __restrict__ dtUh, const float* __restrict__ dtb,
    const float* __restrict__ tdWx, const float* __restrict__ tdUh, const float* __restrict__ tdb,
    const int*   __restrict__ tdpidx, const int* __restrict__ rootidx,
    float* __restrict__ out)
{
    __shared__ float smem[32*132 + 32*128];
    unsigned epoch = 0;

    // ================= bottom-up (DT) pass =================
    gemm_big(emb, NPN, dtWx, dtb, g_XG, smem);      // x @ Wx + b for all nodes
    gbar(&epoch);
    {
        const int nlev = g_nlev_dt;
        gates_range(g_base_dt[0], g_base_dt[1], 0, 0, g_XG, out, g_pairs_dt);  // leaves: h_prev=0
        gbar(&epoch);
        for (int lev = 1; lev < nlev; lev++) {
            int r0 = g_base_dt[lev], r1 = g_base_dt[lev+1];
            gather_dt(r0, r1, out);
            gbar(&epoch);
            gemm512(g_A + (size_t)r0*HN, r1 - r0, dtUh, 0, g_HG + (size_t)r0*H3N, smem);
            gbar(&epoch);
            gates_range(r0, r1, 0, 1, g_XG, out, g_pairs_dt);
            gbar(&epoch);
        }
    }

    // ================= top-down (TD) pass =================
    gemm_big(emb, NPN, tdWx, tdb, g_XG, smem);      // reuse XG buffer
    gbar(&epoch);
    {
        const int nlev = g_nlev_td;
        gates_range(g_base_td[0], g_base_td[1], HN, 0, g_XG, out, g_pairs_td);  // roots: h_prev=0
        gbar(&epoch);
        for (int lev = 1; lev < nlev; lev++) {
            int r0 = g_base_td[lev], r1 = g_base_td[lev+1];
            gather_td(r0, r1, out, tdpidx);
            gbar(&epoch);
            gemm512(g_A + (size_t)r0*HN, r1 - r0, tdUh, 0, g_HG + (size_t)r0*H3N, smem);
            gbar(&epoch);
            gates_range(r0, r1, HN, 1, g_XG, out, g_pairs_td);
            gbar(&epoch);
        }
    }

    // ---- output_t: root rows [1,B,2H] appended after outputs ----
    {
        int gsz = gridDim.x * blockDim.x;
        for (int e = blockIdx.x*blockDim.x + threadIdx.x; e < BN*256; e += gsz) {
            int b = e >> 8, j4 = (e & 255) << 2;
            int rt = rootidx[b];
            float4 v = *(const float4*)&out[(size_t)b*OUTB + (size_t)rt*(2*HN) + j4];
            *(float4*)&out[(size_t)BN*OUTB + (size_t)b*(2*HN) + j4] = v;
        }
    }
}

// =======================================================================
extern "C" void kernel_launch(void* const* d_in, const int* in_sizes, int n_in,
                              void* d_out, int out_size)
{
    (void)in_sizes; (void)n_in; (void)out_size;
    const float* emb     = (const float*)d_in[0];
    // d_in[1] indexes, d_in[2] child_mask, d_in[3] td_node: unused (derivable)
    const int*   tdpidx  = (const int*)  d_in[4];
    const float* tdpval  = (const float*)d_in[5];
    const int*   rootidx = (const int*)  d_in[6];
    const float* dtWx    = (const float*)d_in[7];
    const float* dtUh    = (const float*)d_in[8];
    const float* dtb     = (const float*)d_in[9];
    const float* tdWx    = (const float*)d_in[10];
    const float* tdUh    = (const float*)d_in[11];
    const float* tdb     = (const float*)d_in[12];
    float* out = (float*)d_out;

    int dev = 0, nsm = 148;
    cudaGetDevice(&dev);
    cudaDeviceGetAttribute(&nsm, cudaDevAttrMultiProcessorCount, dev);

    k_sched<<<1, BN>>>(tdpidx, tdpval);
    k_main<<<nsm, 256>>>(emb, dtWx, dtUh, dtb, tdWx, tdUh, tdb, tdpidx, rootidx, out);
}

// round 9
// speedup vs baseline: 1.5653x; 1.5653x over previous
#include <cuda_runtime.h>
#include <cuda_bf16.h>

typedef unsigned long long u64;
typedef unsigned int u32;

#define LN   256
#define BN   128
#define DN   512
#define HN   512
#define H3N  1536
#define NPN  (LN*BN)          // 32768
#define OUTB (LN*2*HN)        // floats per batch in outputs region

// dynamic smem: 1024 align slack + 2 buffers x (A 18432 + B 18432)
#define STG_BYTES   36864
#define DSMEM_BYTES (1024 + 2*STG_BYTES)

// ---------------- device scratch ----------------
__device__ __align__(16) float g_XG[(size_t)NPN*H3N];   // x-projections (reused per pass)
__device__ __align__(16) float g_HG[(size_t)NPN*H3N];   // h@Uh per level
__device__ __align__(16) __nv_bfloat16 g_Eh[(size_t)NPN*DN];
__device__ __align__(16) __nv_bfloat16 g_El[(size_t)NPN*DN];
__device__ __align__(16) __nv_bfloat16 g_Ah[(size_t)NPN*HN];
__device__ __align__(16) __nv_bfloat16 g_Al[(size_t)NPN*HN];
__device__ __align__(16) __nv_bfloat16 g_WT[8][(size_t)H3N*DN]; // {dtWx,dtUh,tdWx,tdUh} x {hi,lo}, [N=1536,K=512]
__device__ unsigned g_pairs_dt[NPN];
__device__ unsigned g_pairs_td[NPN];
__device__ int      g_choff[BN*257];
__device__ int      g_chlist[BN*LN];
__device__ int      g_base_dt[258];
__device__ int      g_base_td[258];
__device__ int      g_nlev_dt;
__device__ int      g_nlev_td;
__device__ unsigned g_bar;

// ---------------- helpers ----------------
__device__ __forceinline__ float sgm(float x) { return 1.0f / (1.0f + __expf(-x)); }
__device__ __forceinline__ float4 f4add(float4 a, float4 b) {
    a.x += b.x; a.y += b.y; a.z += b.z; a.w += b.w; return a;
}
__device__ __forceinline__ u32 smem_u32(const void* p) {
    u32 a;
    asm("{ .reg .u64 t; cvta.to.shared.u64 t, %1; cvt.u32.u64 %0, t; }" : "=r"(a) : "l"(p));
    return a;
}
#define LDSM_X4(r, a) \
    asm volatile("ldmatrix.sync.aligned.m8n8.x4.shared.b16 {%0,%1,%2,%3}, [%4];" \
        : "=r"((r)[0]), "=r"((r)[1]), "=r"((r)[2]), "=r"((r)[3]) : "r"(a))
#define LDSM_X2(r, a) \
    asm volatile("ldmatrix.sync.aligned.m8n8.x2.shared.b16 {%0,%1}, [%2];" \
        : "=r"((r)[0]), "=r"((r)[1]) : "r"(a))
__device__ __forceinline__ void mma16816(float* c, const u32* a, const u32* b) {
    asm volatile("mma.sync.aligned.m16n8k16.row.col.f32.bf16.bf16.f32 "
        "{%0,%1,%2,%3}, {%4,%5,%6,%7}, {%8,%9}, {%0,%1,%2,%3};"
        : "+f"(c[0]), "+f"(c[1]), "+f"(c[2]), "+f"(c[3])
        : "r"(a[0]), "r"(a[1]), "r"(a[2]), "r"(a[3]), "r"(b[0]), "r"(b[1]));
}

// ---------------- grid barrier (1 CTA/SM, all resident) ----------------
__device__ __forceinline__ void gbar(unsigned* ep) {
    __syncthreads();
    if (threadIdx.x == 0) {
        *ep += gridDim.x;
        __threadfence();
        atomicAdd(&g_bar, 1u);
        while (*(volatile unsigned*)&g_bar < *ep) __nanosleep(64);
        __threadfence();
    }
    __syncthreads();
}

// =======================================================================
// Schedule kernel (one block, 128 threads = one tree per thread)
// =======================================================================
__global__ void k_sched(const int* __restrict__ pidx, const float* __restrict__ pval) {
    __shared__ int s_cntd[LN], s_cntt[LN], s_based[257], s_baset[257];
    __shared__ int s_filld[LN], s_fillt[LN];
    __shared__ int s_maxd, s_maxt;
    const int b = threadIdx.x;

    for (int i = b; i < LN; i += BN) { s_cntd[i]=0; s_cntt[i]=0; s_filld[i]=0; s_fillt[i]=0; }
    if (b == 0) { s_maxd = 0; s_maxt = 0; g_bar = 0u; }
    __syncthreads();

    int par[LN]; unsigned char rootf[LN];
    short hl[LN], dl[LN];
    for (int i = 0; i < LN; i++) {
        par[i]   = pidx[i*BN + b];
        rootf[i] = (pval[i*BN + b] == 0.0f) ? 1 : 0;
    }
    for (int i = 0; i < LN; i++) dl[i] = rootf[i] ? 0 : (short)(dl[par[i]] + 1);
    for (int i = 0; i < LN; i++) hl[i] = 0;
    for (int i = LN-1; i >= 1; i--)
        if (!rootf[i]) { short c = (short)(hl[i] + 1); if (c > hl[par[i]]) hl[par[i]] = c; }

    int mxd = 0, mxt = 0;
    for (int i = 0; i < LN; i++) {
        atomicAdd(&s_cntd[hl[i]], 1);
        atomicAdd(&s_cntt[dl[i]], 1);
        if (hl[i] > mxd) mxd = hl[i];
        if (dl[i] > mxt) mxt = dl[i];
    }
    atomicMax(&s_maxd, mxd);
    atomicMax(&s_maxt, mxt);

    int ccnt[LN];
    for (int p = 0; p < LN; p++) ccnt[p] = 0;
    for (int i = 1; i < LN; i++) if (!rootf[i]) ccnt[par[i]]++;
    int cur[LN]; int off = 0;
    for (int p = 0; p < LN; p++) { g_choff[b*257 + p] = off; cur[p] = off; off += ccnt[p]; }
    g_choff[b*257 + 256] = off;
    for (int i = 1; i < LN; i++)
        if (!rootf[i]) { int q = par[i]; g_chlist[b*LN + cur[q]++] = i; }

    __syncthreads();
    if (b == 0) {
        int ad = 0, at = 0;
        for (int l = 0; l < LN; l++) {
            s_based[l] = ad; ad += s_cntd[l];
            s_baset[l] = at; at += s_cntt[l];
        }
        s_based[LN] = ad; s_baset[LN] = at;
        g_nlev_dt = s_maxd + 1;
        g_nlev_td = s_maxt + 1;
        for (int l = 0; l <= LN; l++) { g_base_dt[l] = s_based[l]; g_base_td[l] = s_baset[l]; }
    }
    __syncthreads();

    for (int i = 0; i < LN; i++) {
        int ld = hl[i];
        int k1 = atomicAdd(&s_filld[ld], 1);
        g_pairs_dt[s_based[ld] + k1] = ((unsigned)i << 8) | (unsigned)b;
        int lt = dl[i];
        int k2 = atomicAdd(&s_fillt[lt], 1);
        g_pairs_td[s_baset[lt] + k2] = ((unsigned)i << 8) | (unsigned)b;
    }
}

// =======================================================================
// bf16-split tensor-core GEMM via mma.sync (sm_80+ path, compiles on sm_100):
// C[M x 1536] = Ah·Bh^T + Ah·Bl^T + Al·Bh^T (+ bias), fp32 accumulate.
// K_eff = 24 chunks of 64: kc 0-7 (Ah,Bh), 8-15 (Ah,Bl), 16-23 (Al,Bh).
// CTA tile 128x128; 16 warps 4x4; warp tile 32x32 (2x4 m16n8 frags).
// Double-buffered smem (144B padded rows), register-staged global loads.
// =======================================================================
__device__ void gemm_mma(const __nv_bfloat16* __restrict__ Ah, const __nv_bfloat16* __restrict__ Al,
                         int M,
                         const __nv_bfloat16* __restrict__ Bh, const __nv_bfloat16* __restrict__ Bl,
                         const float* __restrict__ bias, float* __restrict__ C,
                         char* sal, u32 asb)
{
    const int tid  = threadIdx.x;
    const int wid  = tid >> 5, lane = tid & 31;
    const int mrow = (wid >> 2) << 5;        // warp row offset in tile
    const int ncol = (wid & 3) << 5;         // warp col offset in tile
    const int mt = (M + 127) >> 7;
    const int total = mt * 12;

    for (int t = blockIdx.x; t < total; t += gridDim.x) {
        const int row0 = (t / 12) << 7;
        const int col0 = (t % 12) << 7;

        float acc[2][4][4];
        #pragma unroll
        for (int mi = 0; mi < 2; mi++)
            #pragma unroll
            for (int nj = 0; nj < 4; nj++)
                #pragma unroll
                for (int q = 0; q < 4; q++) acc[mi][nj][q] = 0.0f;

        uint4 ra[2], rb[2];
        const uint4 z4 = make_uint4(0u, 0u, 0u, 0u);

        auto ldA = [&](int kc) {
            const __nv_bfloat16* Asrc = (kc < 16) ? Ah : Al;
            int koff = (kc < 16) ? ((kc & 7) << 6) : ((kc - 16) << 6);
            #pragma unroll
            for (int i = 0; i < 2; i++) {
                int u = tid + (i << 9);          // 0..1023
                int row = u >> 3, kq = u & 7;
                int gr = row0 + row;
                ra[i] = (gr < M) ? *(const uint4*)&Asrc[((size_t)gr << 9) + koff + (kq << 3)] : z4;
            }
        };
        auto ldB = [&](int kc) {
            const __nv_bfloat16* Bsrc; int koff;
            if (kc < 8)       { Bsrc = Bh; koff = kc << 6; }
            else if (kc < 16) { Bsrc = Bl; koff = (kc - 8) << 6; }
            else              { Bsrc = Bh; koff = (kc - 16) << 6; }
            #pragma unroll
            for (int i = 0; i < 2; i++) {
                int u = tid + (i << 9);
                int row = u >> 3, kq = u & 7;
                int gn = col0 + row;             // always < 1536
                rb[i] = *(const uint4*)&Bsrc[((size_t)gn << 9) + koff + (kq << 3)];
            }
        };
        auto stAB = [&](int p) {
            char* As = sal + p * STG_BYTES;
            char* Bs = As + 18432;
            #pragma unroll
            for (int i = 0; i < 2; i++) {
                int u = tid + (i << 9);
                int row = u >> 3, kq = u & 7;
                *(uint4*)(As + row * 144 + (kq << 4)) = ra[i];
                *(uint4*)(Bs + row * 144 + (kq << 4)) = rb[i];
            }
        };

        ldA(0); ldB(0);
        __syncthreads();     // protect smem from previous tile's readers
        stAB(0);
        __syncthreads();

        for (int kc = 0; kc < 24; kc++) {
            const int p = kc & 1;
            if (kc < 23) { ldA(kc + 1); ldB(kc + 1); }

            const u32 baseA = asb + p * STG_BYTES;
            const u32 baseB = baseA + 18432;
            #pragma unroll
            for (int s = 0; s < 4; s++) {
                const int k0 = s << 4;
                u32 a0[4], a1[4];
                {
                    int r  = (lane & 7) + ((lane >> 3) & 1) * 8;
                    int kk = (lane >> 4) * 8;
                    u32 ad = baseA + (u32)(mrow + r) * 144u + (u32)(k0 + kk) * 2u;
                    LDSM_X4(a0, ad);
                    LDSM_X4(a1, ad + 16u * 144u);
                }
                u32 b[4][2];
                {
                    int rr  = lane & 7;
                    int kk2 = ((lane >> 3) & 1) * 8;
                    #pragma unroll
                    for (int nj = 0; nj < 4; nj++) {
                        u32 ad = baseB + (u32)(ncol + nj * 8 + rr) * 144u + (u32)(k0 + kk2) * 2u;
                        LDSM_X2(b[nj], ad);
                    }
                }
                #pragma unroll
                for (int nj = 0; nj < 4; nj++) {
                    mma16816(acc[0][nj], a0, b[nj]);
                    mma16816(acc[1][nj], a1, b[nj]);
                }
            }

            if (kc < 23) { __syncthreads(); stAB(p ^ 1); __syncthreads(); }
        }

        // epilogue
        #pragma unroll
        for (int mi = 0; mi < 2; mi++) {
            int gr = row0 + mrow + mi * 16 + (lane >> 2);
            #pragma unroll
            for (int nj = 0; nj < 4; nj++) {
                int gc = col0 + ncol + nj * 8 + ((lane & 3) << 1);
                float bx = 0.0f, by = 0.0f;
                if (bias) { float2 bb = *(const float2*)&bias[gc]; bx = bb.x; by = bb.y; }
                if (gr < M)
                    *(float2*)&C[(size_t)gr * H3N + gc] =
                        make_float2(acc[mi][nj][0] + bx, acc[mi][nj][1] + by);
                if (gr + 8 < M)
                    *(float2*)&C[(size_t)(gr + 8) * H3N + gc] =
                        make_float2(acc[mi][nj][2] + bx, acc[mi][nj][3] + by);
            }
        }
    }
}

// ---------------- split helpers ----------------
__device__ __forceinline__ void wsplit4(size_t base, float4 v) {
    __nv_bfloat16 hx = __float2bfloat16(v.x), hy = __float2bfloat16(v.y);
    __nv_bfloat16 hz = __float2bfloat16(v.z), hw = __float2bfloat16(v.w);
    __nv_bfloat16 lx = __float2bfloat16(v.x - __bfloat162float(hx));
    __nv_bfloat16 ly = __float2bfloat16(v.y - __bfloat162float(hy));
    __nv_bfloat16 lz = __float2bfloat16(v.z - __bfloat162float(hz));
    __nv_bfloat16 lw = __float2bfloat16(v.w - __bfloat162float(hw));
    __nv_bfloat162 h01, h23, l01, l23;
    h01.x = hx; h01.y = hy; h23.x = hz; h23.y = hw;
    l01.x = lx; l01.y = ly; l23.x = lz; l23.y = lw;
    *(__nv_bfloat162*)&g_Ah[base]     = h01;
    *(__nv_bfloat162*)&g_Ah[base + 2] = h23;
    *(__nv_bfloat162*)&g_Al[base]     = l01;
    *(__nv_bfloat162*)&g_Al[base + 2] = l23;
}

// ---------------- gather phases (write bf16 split rows) ----------------
__device__ void gather_dt(int r0, int r1, const float* __restrict__ out)
{
    int g = blockIdx.x*blockDim.x + threadIdx.x;
    int lane = g & 31, warp = g >> 5, nw = (gridDim.x*blockDim.x) >> 5;
    for (int row = r0 + warp; row < r1; row += nw) {
        unsigned p = g_pairs_dt[row]; int node = p >> 8, b = p & 255;
        int cs = g_choff[b*257 + node], ce = g_choff[b*257 + node + 1];
        float4 a0 = make_float4(0,0,0,0), a1 = a0, a2 = a0, a3 = a0;
        for (int c = cs; c < ce; c++) {
            const float4* src = (const float4*)&out[(size_t)b*OUTB + (size_t)g_chlist[b*LN + c]*(2*HN)];
            a0 = f4add(a0, src[lane]);
            a1 = f4add(a1, src[lane + 32]);
            a2 = f4add(a2, src[lane + 64]);
            a3 = f4add(a3, src[lane + 96]);
        }
        size_t rb = (size_t)row * HN;
        wsplit4(rb + (lane << 2), a0);
        wsplit4(rb + ((lane + 32) << 2), a1);
        wsplit4(rb + ((lane + 64) << 2), a2);
        wsplit4(rb + ((lane + 96) << 2), a3);
    }
}

__device__ void gather_td(int r0, int r1, const float* __restrict__ out,
                          const int* __restrict__ pidx)
{
    int g = blockIdx.x*blockDim.x + threadIdx.x;
    int lane = g & 31, warp = g >> 5, nw = (gridDim.x*blockDim.x) >> 5;
    for (int row = r0 + warp; row < r1; row += nw) {
        unsigned p = g_pairs_td[row]; int node = p >> 8, b = p & 255;
        int parent = pidx[node*BN + b];
        const float4* src = (const float4*)&out[(size_t)b*OUTB + (size_t)parent*(2*HN) + HN];
        size_t rb = (size_t)row * HN;
        wsplit4(rb + (lane << 2),        src[lane]);
        wsplit4(rb + ((lane + 32) << 2), src[lane + 32]);
        wsplit4(rb + ((lane + 64) << 2), src[lane + 64]);
        wsplit4(rb + ((lane + 96) << 2), src[lane + 96]);
    }
}

// ---------------- gate epilogue ----------------
__device__ void gates_range(int r0, int r1, int passoff, int haveH,
                            const float* __restrict__ xgb, float* __restrict__ out,
                            const unsigned* __restrict__ pairs)
{
    int total = (r1 - r0) << 7;   // float4 elements
    int gsz = gridDim.x * blockDim.x;
    for (int e = blockIdx.x*blockDim.x + threadIdx.x; e < total; e += gsz) {
        int row = r0 + (e >> 7);
        int j4  = (e & 127) << 2;
        unsigned p = pairs[row]; int node = p >> 8, b = p & 255;
        const float* xg = xgb + (size_t)(node*BN + b) * H3N;
        float4 xr = *(const float4*)&xg[j4];
        float4 xz = *(const float4*)&xg[HN + j4];
        float4 xn = *(const float4*)&xg[2*HN + j4];
        float4 hr = make_float4(0,0,0,0), hz = hr, hn = hr, hp = hr;
        if (haveH) {
            const float* hg = g_HG + (size_t)row * H3N;
            hr = *(const float4*)&hg[j4];
            hz = *(const float4*)&hg[HN + j4];
            hn = *(const float4*)&hg[2*HN + j4];
            const __nv_bfloat162* bh = (const __nv_bfloat162*)&g_Ah[(size_t)row*HN + j4];
            const __nv_bfloat162* bl = (const __nv_bfloat162*)&g_Al[(size_t)row*HN + j4];
            __nv_bfloat162 h0 = bh[0], h1 = bh[1], l0 = bl[0], l1 = bl[1];
            hp.x = __bfloat162float(h0.x) + __bfloat162float(l0.x);
            hp.y = __bfloat162float(h0.y) + __bfloat162float(l0.y);
            hp.z = __bfloat162float(h1.x) + __bfloat162float(l1.x);
            hp.w = __bfloat162float(h1.y) + __bfloat162float(l1.y);
        }
        float4 o;
        { float r_=sgm(xr.x+hr.x), z_=sgm(xz.x+hz.x), n_=tanhf(xn.x + r_*hn.x); o.x=(1.f-z_)*n_ + z_*hp.x; }
        { float r_=sgm(xr.y+hr.y), z_=sgm(xz.y+hz.y), n_=tanhf(xn.y + r_*hn.y); o.y=(1.f-z_)*n_ + z_*hp.y; }
        { float r_=sgm(xr.z+hr.z), z_=sgm(xz.z+hz.z), n_=tanhf(xn.z + r_*hn.z); o.z=(1.f-z_)*n_ + z_*hp.z; }
        { float r_=sgm(xr.w+hr.w), z_=sgm(xz.w+hz.w), n_=tanhf(xn.w + r_*hn.w); o.w=(1.f-z_)*n_ + z_*hp.w; }
        *(float4*)&out[(size_t)b*OUTB + (size_t)node*(2*HN) + passoff + j4] = o;
    }
}

// =======================================================================
// Persistent main kernel.
// =======================================================================
__global__ void __launch_bounds__(512, 1) k_main(
    const float* __restrict__ emb,
    const float* __restrict__ dtWx, const float* __restrict__ dtUh, const float* __restrict__ dtb,
    const float* __restrict__ tdWx, const float* __restrict__ tdUh, const float* __restrict__ tdb,
    const int*   __restrict__ tdpidx, const int* __restrict__ rootidx,
    float* __restrict__ out)
{
    extern __shared__ char dsm[];
    char* sal = (char*)(((u64)(dsm) + 1023ULL) & ~1023ULL);
    u32 asb = smem_u32(sal);
    const int tid = threadIdx.x;
    unsigned epoch = 0;

    // ---- phase 0: split emb; transpose+split all four weight matrices ----
    {
        int gt = blockIdx.x*blockDim.x + tid, gsz = gridDim.x*blockDim.x;
        for (int i = gt; i < NPN*DN; i += gsz) {
            float v = emb[i];
            __nv_bfloat16 h = __float2bfloat16(v);
            g_Eh[i] = h;
            g_El[i] = __float2bfloat16(v - __bfloat162float(h));
        }
        const float* Ws[4] = { dtWx, dtUh, tdWx, tdUh };
        for (int m = 0; m < 4; m++) {
            const float* W = Ws[m];
            __nv_bfloat16* th = g_WT[2*m];
            __nv_bfloat16* tl = g_WT[2*m+1];
            for (int i = gt; i < H3N*DN; i += gsz) {
                int n = i >> 9, k = i & 511;
                float v = W[(size_t)k*H3N + n];
                __nv_bfloat16 h = __float2bfloat16(v);
                th[i] = h;
                tl[i] = __float2bfloat16(v - __bfloat162float(h));
            }
        }
    }
    gbar(&epoch);

    // ================= bottom-up (DT) pass =================
    gemm_mma(g_Eh, g_El, NPN, g_WT[0], g_WT[1], dtb, g_XG, sal, asb);
    gbar(&epoch);
    gates_range(g_base_dt[0], g_base_dt[1], 0, 0, g_XG, out, g_pairs_dt);  // leaves
    gbar(&epoch);
    for (int lev = 1; lev < g_nlev_dt; lev++) {
        int r0 = g_base_dt[lev], r1 = g_base_dt[lev+1];
        gather_dt(r0, r1, out);
        gbar(&epoch);
        gemm_mma(g_Ah + ((size_t)r0 << 9), g_Al + ((size_t)r0 << 9), r1 - r0,
                 g_WT[2], g_WT[3], 0, g_HG + (size_t)r0*H3N, sal, asb);
        gbar(&epoch);
        gates_range(r0, r1, 0, 1, g_XG, out, g_pairs_dt);
        gbar(&epoch);
    }

    // ================= top-down (TD) pass =================
    gemm_mma(g_Eh, g_El, NPN, g_WT[4], g_WT[5], tdb, g_XG, sal, asb);
    gbar(&epoch);
    gates_range(g_base_td[0], g_base_td[1], HN, 0, g_XG, out, g_pairs_td);  // roots
    gbar(&epoch);
    for (int lev = 1; lev < g_nlev_td; lev++) {
        int r0 = g_base_td[lev], r1 = g_base_td[lev+1];
        gather_td(r0, r1, out, tdpidx);
        gbar(&epoch);
        gemm_mma(g_Ah + ((size_t)r0 << 9), g_Al + ((size_t)r0 << 9), r1 - r0,
                 g_WT[6], g_WT[7], 0, g_HG + (size_t)r0*H3N, sal, asb);
        gbar(&epoch);
        gates_range(r0, r1, HN, 1, g_XG, out, g_pairs_td);
        gbar(&epoch);
    }

    // ---- output_t: root rows [1,B,2H] appended after outputs ----
    {
        int gsz = gridDim.x * blockDim.x;
        for (int e = blockIdx.x*blockDim.x + tid; e < BN*256; e += gsz) {
            int b = e >> 8, j4 = (e & 255) << 2;
            int rt = rootidx[b];
            float4 v = *(const float4*)&out[(size_t)b*OUTB + (size_t)rt*(2*HN) + j4];
            *(float4*)&out[(size_t)BN*OUTB + (size_t)b*(2*HN) + j4] = v;
        }
    }
}

// =======================================================================
extern "C" void kernel_launch(void* const* d_in, const int* in_sizes, int n_in,
                              void* d_out, int out_size)
{
    (void)in_sizes; (void)n_in; (void)out_size;
    const float* emb     = (const float*)d_in[0];
    const int*   tdpidx  = (const int*)  d_in[4];
    const float* tdpval  = (const float*)d_in[5];
    const int*   rootidx = (const int*)  d_in[6];
    const float* dtWx    = (const float*)d_in[7];
    const float* dtUh    = (const float*)d_in[8];
    const float* dtb     = (const float*)d_in[9];
    const float* tdWx    = (const float*)d_in[10];
    const float* tdUh    = (const float*)d_in[11];
    const float* tdb     = (const float*)d_in[12];
    float* out = (float*)d_out;

    int dev = 0, nsm = 148;
    cudaGetDevice(&dev);
    cudaDeviceGetAttribute(&nsm, cudaDevAttrMultiProcessorCount, dev);

    cudaFuncSetAttribute(k_main, cudaFuncAttributeMaxDynamicSharedMemorySize, DSMEM_BYTES);

    k_sched<<<1, BN>>>(tdpidx, tdpval);
    k_main<<<nsm, 512, DSMEM_BYTES>>>(emb, dtWx, dtUh, dtb, tdWx, tdUh, tdb, tdpidx, rootidx, out);
}